// round 2
// baseline (speedup 1.0000x reference)
#include <cuda_runtime.h>

#define L    1024
#define DM   1024
#define DI   2048
#define E2   4096
#define NB   2
#define DS   16

// ---------------- scratch (static device globals; no allocation) ----------------
__device__ float g_xz[NB * E2 * L];         // [b][e][l]      32 MB
__device__ float g_xconv[2][NB * DI * L];   // per dir [b][c][t] (logical time)
__device__ float g_xdbl[2][NB * 96 * L];    // per dir [b][row96][t]
__device__ float g_delta[2][NB * DI * L];
__device__ float g_y[2][NB * DI * L];
__device__ float g_comb[NB * DI * L];

__device__ __forceinline__ float siluf(float v) {
    return v / (1.f + __expf(-v));
}
__device__ __forceinline__ float softplusf(float v) {
    return v > 20.f ? v : log1pf(__expf(v));
}

// =====================================================================
// GEMM 1: xz[b,e,l] = sum_d hs[b,l,d] * Win[e,d]
// M=2048 (b,l), N=4096 (e), K=1024. A row-major, B row-major (NT).
// =====================================================================
__global__ __launch_bounds__(256) void k_inproj(const float* __restrict__ A,
                                                const float* __restrict__ W) {
    __shared__ float As[8][128];
    __shared__ float Bs[8][128];
    const int tid = threadIdx.x;
    const int tx = tid & 15, ty = tid >> 4;
    const int bm = blockIdx.y * 128;
    const int bn = blockIdx.x * 128;
    const int ar = tid >> 1, ac = (tid & 1) * 4;

    float acc[8][8];
#pragma unroll
    for (int i = 0; i < 8; i++)
#pragma unroll
        for (int j = 0; j < 8; j++) acc[i][j] = 0.f;

    for (int k0 = 0; k0 < DM; k0 += 8) {
        float4 av = *(const float4*)(A + (size_t)(bm + ar) * DM + k0 + ac);
        float4 bv = *(const float4*)(W + (size_t)(bn + ar) * DM + k0 + ac);
        As[ac + 0][ar] = av.x; As[ac + 1][ar] = av.y;
        As[ac + 2][ar] = av.z; As[ac + 3][ar] = av.w;
        Bs[ac + 0][ar] = bv.x; Bs[ac + 1][ar] = bv.y;
        Bs[ac + 2][ar] = bv.z; Bs[ac + 3][ar] = bv.w;
        __syncthreads();
#pragma unroll
        for (int kk = 0; kk < 8; kk++) {
            float a[8], b[8];
            *(float4*)(a)     = *(const float4*)&As[kk][ty * 4];
            *(float4*)(a + 4) = *(const float4*)&As[kk][64 + ty * 4];
            *(float4*)(b)     = *(const float4*)&Bs[kk][tx * 4];
            *(float4*)(b + 4) = *(const float4*)&Bs[kk][64 + tx * 4];
#pragma unroll
            for (int i = 0; i < 8; i++)
#pragma unroll
                for (int j = 0; j < 8; j++) acc[i][j] = fmaf(a[i], b[j], acc[i][j]);
        }
        __syncthreads();
    }

    // scatter store: xz[b][n][l], l contiguous along m
    const int bb = bm >> 10;
    const int l0 = bm & 1023;
#pragma unroll
    for (int j = 0; j < 8; j++) {
        int n = bn + ((j < 4) ? (tx * 4 + j) : (64 + tx * 4 + j - 4));
        float* dst = g_xz + ((size_t)(bb * E2 + n)) * L + l0;
        float4 v0 = make_float4(acc[0][j], acc[1][j], acc[2][j], acc[3][j]);
        float4 v1 = make_float4(acc[4][j], acc[5][j], acc[6][j], acc[7][j]);
        *(float4*)(dst + ty * 4) = v0;
        *(float4*)(dst + 64 + ty * 4) = v1;
    }
}

// =====================================================================
// Depthwise causal conv (D_CONV=4) + silu, into logical-time layout
// =====================================================================
__global__ __launch_bounds__(256) void k_conv(const float* __restrict__ cw,
                                              const float* __restrict__ cb,
                                              int dir) {
    const int t = blockIdx.x * 256 + threadIdx.x;   // logical time
    const int c = blockIdx.y;
    const int b = blockIdx.z;
    const float* xr = g_xz + ((size_t)(b * E2 + c)) * L;
    float acc = cb[c];
#pragma unroll
    for (int j = 0; j < 4; j++) {
        int tt = t - 3 + j;
        if (tt >= 0) {
            int ph = dir ? (L - 1 - tt) : tt;
            acc = fmaf(cw[c * 4 + j], xr[ph], acc);
        }
    }
    g_xconv[dir][((size_t)(b * DI + c)) * L + t] = siluf(acc);
}

// =====================================================================
// GEMM 2: xdbl[b,e,t] = sum_c Wp[e,c] * xconv[b,c,t]   (M=96 padded to 128)
// =====================================================================
__global__ __launch_bounds__(256) void k_xproj(const float* __restrict__ Wp, int dir) {
    __shared__ float As[8][128];
    __shared__ float Bs[8][128];
    const int tid = threadIdx.x;
    const int tx = tid & 15, ty = tid >> 4;
    const int bn = blockIdx.x * 128;
    const int b = blockIdx.z;
    const int ar = tid >> 1, ac = (tid & 1) * 4;
    const int kr = tid >> 5, nc = (tid & 31) * 4;
    const float* X = g_xconv[dir] + (size_t)b * DI * L;

    float acc[8][8];
#pragma unroll
    for (int i = 0; i < 8; i++)
#pragma unroll
        for (int j = 0; j < 8; j++) acc[i][j] = 0.f;

    for (int k0 = 0; k0 < DI; k0 += 8) {
        float4 av = make_float4(0.f, 0.f, 0.f, 0.f);
        if (ar < 96) av = *(const float4*)(Wp + (size_t)ar * DI + k0 + ac);
        As[ac + 0][ar] = av.x; As[ac + 1][ar] = av.y;
        As[ac + 2][ar] = av.z; As[ac + 3][ar] = av.w;
        float4 bv = *(const float4*)(X + (size_t)(k0 + kr) * L + bn + nc);
        *(float4*)&Bs[kr][nc] = bv;
        __syncthreads();
#pragma unroll
        for (int kk = 0; kk < 8; kk++) {
            float a[8], bfr[8];
            *(float4*)(a)       = *(const float4*)&As[kk][ty * 4];
            *(float4*)(a + 4)   = *(const float4*)&As[kk][64 + ty * 4];
            *(float4*)(bfr)     = *(const float4*)&Bs[kk][tx * 4];
            *(float4*)(bfr + 4) = *(const float4*)&Bs[kk][64 + tx * 4];
#pragma unroll
            for (int i = 0; i < 8; i++)
#pragma unroll
                for (int j = 0; j < 8; j++) acc[i][j] = fmaf(a[i], bfr[j], acc[i][j]);
        }
        __syncthreads();
    }

    float* dstb = g_xdbl[dir] + (size_t)b * 96 * L;
#pragma unroll
    for (int i = 0; i < 8; i++) {
        int m = (i < 4) ? (ty * 4 + i) : (64 + ty * 4 + i - 4);
        if (m < 96) {
            float4 v0 = make_float4(acc[i][0], acc[i][1], acc[i][2], acc[i][3]);
            float4 v1 = make_float4(acc[i][4], acc[i][5], acc[i][6], acc[i][7]);
            *(float4*)(dstb + (size_t)m * L + bn + tx * 4) = v0;
            *(float4*)(dstb + (size_t)m * L + bn + 64 + tx * 4) = v1;
        }
    }
}

// =====================================================================
// GEMM 3: delta[b,d,t] = softplus( sum_r Wd[d,r]*xdbl[b,r,t] + bias[d] )
// M=2048, N=1024, K=64
// =====================================================================
__global__ __launch_bounds__(256) void k_dtproj(const float* __restrict__ Wd,
                                                const float* __restrict__ bd,
                                                int dir) {
    __shared__ float As[8][128];
    __shared__ float Bs[8][128];
    const int tid = threadIdx.x;
    const int tx = tid & 15, ty = tid >> 4;
    const int bm = blockIdx.y * 128;
    const int bn = blockIdx.x * 128;
    const int b = blockIdx.z;
    const int ar = tid >> 1, ac = (tid & 1) * 4;
    const int kr = tid >> 5, nc = (tid & 31) * 4;
    const float* Bmat = g_xdbl[dir] + (size_t)b * 96 * L;   // rows 0..63 = dtr

    float acc[8][8];
#pragma unroll
    for (int i = 0; i < 8; i++)
#pragma unroll
        for (int j = 0; j < 8; j++) acc[i][j] = 0.f;

    for (int k0 = 0; k0 < 64; k0 += 8) {
        float4 av = *(const float4*)(Wd + (size_t)(bm + ar) * 64 + k0 + ac);
        As[ac + 0][ar] = av.x; As[ac + 1][ar] = av.y;
        As[ac + 2][ar] = av.z; As[ac + 3][ar] = av.w;
        float4 bv = *(const float4*)(Bmat + (size_t)(k0 + kr) * L + bn + nc);
        *(float4*)&Bs[kr][nc] = bv;
        __syncthreads();
#pragma unroll
        for (int kk = 0; kk < 8; kk++) {
            float a[8], bfr[8];
            *(float4*)(a)       = *(const float4*)&As[kk][ty * 4];
            *(float4*)(a + 4)   = *(const float4*)&As[kk][64 + ty * 4];
            *(float4*)(bfr)     = *(const float4*)&Bs[kk][tx * 4];
            *(float4*)(bfr + 4) = *(const float4*)&Bs[kk][64 + tx * 4];
#pragma unroll
            for (int i = 0; i < 8; i++)
#pragma unroll
                for (int j = 0; j < 8; j++) acc[i][j] = fmaf(a[i], bfr[j], acc[i][j]);
        }
        __syncthreads();
    }

    float* dstb = g_delta[dir] + (size_t)b * DI * L;
#pragma unroll
    for (int i = 0; i < 8; i++) {
        int m = bm + ((i < 4) ? (ty * 4 + i) : (64 + ty * 4 + i - 4));
        float bias = bd[m];
        float4 v0 = make_float4(softplusf(acc[i][0] + bias), softplusf(acc[i][1] + bias),
                                softplusf(acc[i][2] + bias), softplusf(acc[i][3] + bias));
        float4 v1 = make_float4(softplusf(acc[i][4] + bias), softplusf(acc[i][5] + bias),
                                softplusf(acc[i][6] + bias), softplusf(acc[i][7] + bias));
        *(float4*)(dstb + (size_t)m * L + bn + tx * 4) = v0;
        *(float4*)(dstb + (size_t)m * L + bn + 64 + tx * 4) = v1;
    }
}

// =====================================================================
// Selective scan: half-warp per (b,d); lane n in [0,16) owns state n.
//  h_n = exp(delta*A_n)*h_n + delta*B_n*x ;  y = sum_n h_n*C_n + x*D
// =====================================================================
__global__ __launch_bounds__(256) void k_scan(const float* __restrict__ Alog,
                                              const float* __restrict__ Dp,
                                              int dir) {
    const int gt = blockIdx.x * 256 + threadIdx.x;
    const int n = gt & 15;
    const int p = gt >> 4;          // 0..4095  = b*DI + d
    const int b = p >> 11;
    const int d = p & 2047;

    const float An = -expf(Alog[d * DS + n]);
    const float Dd = Dp[d];
    const float* del = g_delta[dir] + ((size_t)(b * DI + d)) * L;
    const float* xx  = g_xconv[dir] + ((size_t)(b * DI + d)) * L;
    const float* Bm  = g_xdbl[dir]  + ((size_t)(b * 96 + 64 + n)) * L;
    const float* Cm  = g_xdbl[dir]  + ((size_t)(b * 96 + 80 + n)) * L;
    float* yo = g_y[dir] + ((size_t)(b * DI + d)) * L;

    float h = 0.f;
#pragma unroll 4
    for (int t = 0; t < L; t++) {
        float dl = del[t];
        float xv = xx[t];
        float dA = __expf(dl * An);
        h = fmaf(dA, h, dl * Bm[t] * xv);
        float s = h * Cm[t];
        s += __shfl_xor_sync(0xffffffffu, s, 1);
        s += __shfl_xor_sync(0xffffffffu, s, 2);
        s += __shfl_xor_sync(0xffffffffu, s, 4);
        s += __shfl_xor_sync(0xffffffffu, s, 8);
        if (n == 0) yo[t] = fmaf(xv, Dd, s);
    }
}

// =====================================================================
// Combine: comb[b,d,l] = 0.5*silu(z[b,d,l]) * (y_f[b,d,l] + y_b[b,d,L-1-l])
// =====================================================================
__global__ __launch_bounds__(256) void k_combine() {
    size_t idx = (size_t)blockIdx.x * 256 + threadIdx.x;  // over NB*DI*L
    int l = (int)(idx & 1023);
    size_t bd = idx >> 10;             // b*DI + d
    int b = (int)(bd >> 11);
    int d = (int)(bd & 2047);
    float z = g_xz[((size_t)(b * E2 + DI + d)) * L + l];
    float yf = g_y[0][idx];
    float yb = g_y[1][(bd << 10) + (size_t)(1023 - l)];
    g_comb[idx] = 0.5f * siluf(z) * (yf + yb);
}

// =====================================================================
// GEMM 4: Out[b,l,o] = sum_d comb[b,d,l] * Wo[o,d]
// M=2048 (b,l), N=1024 (o), K=2048. A is k-major (contiguous in m!).
// =====================================================================
__global__ __launch_bounds__(256) void k_outproj(const float* __restrict__ Wo,
                                                 float* __restrict__ Out) {
    __shared__ float As[8][128];
    __shared__ float Bs[8][128];
    const int tid = threadIdx.x;
    const int tx = tid & 15, ty = tid >> 4;
    const int bm = blockIdx.y * 128;
    const int bn = blockIdx.x * 128;
    const int ar = tid >> 1, ac = (tid & 1) * 4;
    const int kr = tid >> 5, mc = (tid & 31) * 4;
    const int bb = bm >> 10;
    const int l0 = bm & 1023;
    const float* Abase = g_comb + (size_t)bb * DI * L;

    float acc[8][8];
#pragma unroll
    for (int i = 0; i < 8; i++)
#pragma unroll
        for (int j = 0; j < 8; j++) acc[i][j] = 0.f;

    for (int k0 = 0; k0 < DI; k0 += 8) {
        float4 av = *(const float4*)(Abase + (size_t)(k0 + kr) * L + l0 + mc);
        *(float4*)&As[kr][mc] = av;
        float4 bv = *(const float4*)(Wo + (size_t)(bn + ar) * DI + k0 + ac);
        Bs[ac + 0][ar] = bv.x; Bs[ac + 1][ar] = bv.y;
        Bs[ac + 2][ar] = bv.z; Bs[ac + 3][ar] = bv.w;
        __syncthreads();
#pragma unroll
        for (int kk = 0; kk < 8; kk++) {
            float a[8], bfr[8];
            *(float4*)(a)       = *(const float4*)&As[kk][ty * 4];
            *(float4*)(a + 4)   = *(const float4*)&As[kk][64 + ty * 4];
            *(float4*)(bfr)     = *(const float4*)&Bs[kk][tx * 4];
            *(float4*)(bfr + 4) = *(const float4*)&Bs[kk][64 + tx * 4];
#pragma unroll
            for (int i = 0; i < 8; i++)
#pragma unroll
                for (int j = 0; j < 8; j++) acc[i][j] = fmaf(a[i], bfr[j], acc[i][j]);
        }
        __syncthreads();
    }

#pragma unroll
    for (int i = 0; i < 8; i++) {
        int m = bm + ((i < 4) ? (ty * 4 + i) : (64 + ty * 4 + i - 4));
        float4 v0 = make_float4(acc[i][0], acc[i][1], acc[i][2], acc[i][3]);
        float4 v1 = make_float4(acc[i][4], acc[i][5], acc[i][6], acc[i][7]);
        *(float4*)(Out + (size_t)m * DM + bn + tx * 4) = v0;
        *(float4*)(Out + (size_t)m * DM + bn + 64 + tx * 4) = v1;
    }
}

// =====================================================================
extern "C" void kernel_launch(void* const* d_in, const int* in_sizes, int n_in,
                              void* d_out, int out_size) {
    const float* hs   = (const float*)d_in[0];
    const float* Win  = (const float*)d_in[1];
    const float* cw[2]  = {(const float*)d_in[2],  (const float*)d_in[9]};
    const float* cb[2]  = {(const float*)d_in[3],  (const float*)d_in[10]};
    const float* xpw[2] = {(const float*)d_in[4],  (const float*)d_in[11]};
    const float* dtw[2] = {(const float*)d_in[5],  (const float*)d_in[12]};
    const float* dtb[2] = {(const float*)d_in[6],  (const float*)d_in[13]};
    const float* al[2]  = {(const float*)d_in[7],  (const float*)d_in[14]};
    const float* dp[2]  = {(const float*)d_in[8],  (const float*)d_in[15]};
    const float* Wout = (const float*)d_in[16];
    float* Out = (float*)d_out;

    k_inproj<<<dim3(32, 16), 256>>>(hs, Win);
    for (int dir = 0; dir < 2; dir++) {
        k_conv<<<dim3(4, DI, NB), 256>>>(cw[dir], cb[dir], dir);
        k_xproj<<<dim3(8, 1, NB), 256>>>(xpw[dir], dir);
        k_dtproj<<<dim3(8, 16, NB), 256>>>(dtw[dir], dtb[dir], dir);
        k_scan<<<256, 256>>>(al[dir], dp[dir], dir);
    }
    k_combine<<<16384, 256>>>();
    k_outproj<<<dim3(8, 16), 256>>>(Wout, Out);
}

// round 4
// speedup vs baseline: 1.1179x; 1.1179x over previous
#include <cuda_runtime.h>

#define L    1024
#define DM   1024
#define DI   2048
#define E2   4096
#define NB   2
#define DS   16

// ---------------- scratch (static device globals; no allocation) ----------------
__device__ float g_xz[NB * E2 * L];         // [b][e][l]
__device__ float g_xconv[2][NB * DI * L];   // per dir [b][c][t] (logical time)
__device__ float g_xdbl[2][NB * 96 * L];    // per dir [b][row96][t]
__device__ float g_delta[2][NB * DI * L];
__device__ float g_y[2][NB * DI * L];
__device__ float g_comb[NB * DI * L];

__device__ __forceinline__ float siluf(float v) {
    return v / (1.f + __expf(-v));
}
__device__ __forceinline__ float softplusf(float v) {
    return v > 20.f ? v : log1pf(__expf(v));
}

// ---------------- packed f32x2 FMA helpers (FFMA2, PTX-only) ----------------
__device__ __forceinline__ void fma2(unsigned long long& d, unsigned long long a,
                                     unsigned long long b) {
    asm("fma.rn.f32x2 %0, %1, %2, %0;" : "+l"(d) : "l"(a), "l"(b));
}
__device__ __forceinline__ unsigned long long pack2(float x, float y) {
    unsigned long long r;
    asm("mov.b64 %0, {%1, %2};" : "=l"(r) : "f"(x), "f"(y));
    return r;
}
__device__ __forceinline__ void unpack2(unsigned long long v, float& x, float& y) {
    asm("mov.b64 {%0, %1}, %2;" : "=f"(x), "=f"(y) : "l"(v));
}

// Shared 8x8 microkernel body over one smem K-slab (8 deep), packed accumulators.
// acc[i][j2] holds columns (j2*2, j2*2+1) of the 8-wide column group for row i.
#define MICRO_KK(As, Bs, acc)                                                  \
    _Pragma("unroll")                                                          \
    for (int kk = 0; kk < 8; kk++) {                                           \
        float a[8];                                                            \
        *(float4*)(a)     = *(const float4*)&As[kk][ty * 4];                   \
        *(float4*)(a + 4) = *(const float4*)&As[kk][64 + ty * 4];              \
        ulonglong2 b01 = *(const ulonglong2*)&Bs[kk][tx * 4];                  \
        ulonglong2 b23 = *(const ulonglong2*)&Bs[kk][64 + tx * 4];             \
        unsigned long long bp0 = b01.x, bp1 = b01.y, bp2 = b23.x, bp3 = b23.y; \
        _Pragma("unroll")                                                      \
        for (int i = 0; i < 8; i++) {                                          \
            unsigned long long ap = pack2(a[i], a[i]);                         \
            fma2(acc[i][0], ap, bp0);                                          \
            fma2(acc[i][1], ap, bp1);                                          \
            fma2(acc[i][2], ap, bp2);                                          \
            fma2(acc[i][3], ap, bp3);                                          \
        }                                                                      \
    }

#define UNPACK_ACC(acc, accf)                                                  \
    _Pragma("unroll")                                                          \
    for (int i = 0; i < 8; i++) {                                              \
        unpack2(acc[i][0], accf[i][0], accf[i][1]);                            \
        unpack2(acc[i][1], accf[i][2], accf[i][3]);                            \
        unpack2(acc[i][2], accf[i][4], accf[i][5]);                            \
        unpack2(acc[i][3], accf[i][6], accf[i][7]);                            \
    }

// =====================================================================
// GEMM 1: xz[b,e,l] = sum_d hs[b,l,d] * Win[e,d]
// M=2048 (b,l), N=4096 (e), K=1024. A row-major, B row-major (NT).
// =====================================================================
__global__ __launch_bounds__(256) void k_inproj(const float* __restrict__ A,
                                                const float* __restrict__ W) {
    __shared__ float As[8][128];
    __shared__ float Bs[8][128];
    const int tid = threadIdx.x;
    const int tx = tid & 15, ty = tid >> 4;
    const int bm = blockIdx.y * 128;
    const int bn = blockIdx.x * 128;
    const int ar = tid >> 1, ac = (tid & 1) * 4;

    unsigned long long acc[8][4];
#pragma unroll
    for (int i = 0; i < 8; i++)
#pragma unroll
        for (int j = 0; j < 4; j++) acc[i][j] = 0ull;

    float4 av = *(const float4*)(A + (size_t)(bm + ar) * DM + ac);
    float4 bv = *(const float4*)(W + (size_t)(bn + ar) * DM + ac);

    for (int k0 = 0; k0 < DM; k0 += 8) {
        As[ac + 0][ar] = av.x; As[ac + 1][ar] = av.y;
        As[ac + 2][ar] = av.z; As[ac + 3][ar] = av.w;
        Bs[ac + 0][ar] = bv.x; Bs[ac + 1][ar] = bv.y;
        Bs[ac + 2][ar] = bv.z; Bs[ac + 3][ar] = bv.w;
        __syncthreads();
        if (k0 + 8 < DM) {
            av = *(const float4*)(A + (size_t)(bm + ar) * DM + k0 + 8 + ac);
            bv = *(const float4*)(W + (size_t)(bn + ar) * DM + k0 + 8 + ac);
        }
        MICRO_KK(As, Bs, acc);
        __syncthreads();
    }

    float accf[8][8];
    UNPACK_ACC(acc, accf);

    // scatter store: xz[b][n][l], l contiguous along m
    const int bb = bm >> 10;
    const int l0 = bm & 1023;
#pragma unroll
    for (int j = 0; j < 8; j++) {
        int n = bn + ((j < 4) ? (tx * 4 + j) : (64 + tx * 4 + j - 4));
        float* dst = g_xz + ((size_t)(bb * E2 + n)) * L + l0;
        float4 v0 = make_float4(accf[0][j], accf[1][j], accf[2][j], accf[3][j]);
        float4 v1 = make_float4(accf[4][j], accf[5][j], accf[6][j], accf[7][j]);
        *(float4*)(dst + ty * 4) = v0;
        *(float4*)(dst + 64 + ty * 4) = v1;
    }
}

// =====================================================================
// Depthwise causal conv (D_CONV=4) + silu, into logical-time layout
// =====================================================================
__global__ __launch_bounds__(256) void k_conv(const float* __restrict__ cw,
                                              const float* __restrict__ cb,
                                              int dir) {
    const int t = blockIdx.x * 256 + threadIdx.x;   // logical time
    const int c = blockIdx.y;
    const int b = blockIdx.z;
    const float* xr = g_xz + ((size_t)(b * E2 + c)) * L;
    float acc = cb[c];
#pragma unroll
    for (int j = 0; j < 4; j++) {
        int tt = t - 3 + j;
        if (tt >= 0) {
            int ph = dir ? (L - 1 - tt) : tt;
            acc = fmaf(cw[c * 4 + j], xr[ph], acc);
        }
    }
    g_xconv[dir][((size_t)(b * DI + c)) * L + t] = siluf(acc);
}

// =====================================================================
// GEMM 2: xdbl[b,e,t] = sum_c Wp[e,c] * xconv[b,c,t]   (M=96 padded to 128)
// =====================================================================
__global__ __launch_bounds__(256) void k_xproj(const float* __restrict__ Wp, int dir) {
    __shared__ float As[8][128];
    __shared__ float Bs[8][128];
    const int tid = threadIdx.x;
    const int tx = tid & 15, ty = tid >> 4;
    const int bn = blockIdx.x * 128;
    const int b = blockIdx.z;
    const int ar = tid >> 1, ac = (tid & 1) * 4;
    const int kr = tid >> 5, nc = (tid & 31) * 4;
    const float* X = g_xconv[dir] + (size_t)b * DI * L;

    unsigned long long acc[8][4];
#pragma unroll
    for (int i = 0; i < 8; i++)
#pragma unroll
        for (int j = 0; j < 4; j++) acc[i][j] = 0ull;

    float4 av = make_float4(0.f, 0.f, 0.f, 0.f);
    if (ar < 96) av = *(const float4*)(Wp + (size_t)ar * DI + ac);
    float4 bv = *(const float4*)(X + (size_t)kr * L + bn + nc);

    for (int k0 = 0; k0 < DI; k0 += 8) {
        As[ac + 0][ar] = av.x; As[ac + 1][ar] = av.y;
        As[ac + 2][ar] = av.z; As[ac + 3][ar] = av.w;
        *(float4*)&Bs[kr][nc] = bv;
        __syncthreads();
        if (k0 + 8 < DI) {
            if (ar < 96) av = *(const float4*)(Wp + (size_t)ar * DI + k0 + 8 + ac);
            bv = *(const float4*)(X + (size_t)(k0 + 8 + kr) * L + bn + nc);
        }
        MICRO_KK(As, Bs, acc);
        __syncthreads();
    }

    float accf[8][8];
    UNPACK_ACC(acc, accf);

    float* dstb = g_xdbl[dir] + (size_t)b * 96 * L;
#pragma unroll
    for (int i = 0; i < 8; i++) {
        int m = (i < 4) ? (ty * 4 + i) : (64 + ty * 4 + i - 4);
        if (m < 96) {
            float4 v0 = make_float4(accf[i][0], accf[i][1], accf[i][2], accf[i][3]);
            float4 v1 = make_float4(accf[i][4], accf[i][5], accf[i][6], accf[i][7]);
            *(float4*)(dstb + (size_t)m * L + bn + tx * 4) = v0;
            *(float4*)(dstb + (size_t)m * L + bn + 64 + tx * 4) = v1;
        }
    }
}

// =====================================================================
// GEMM 3: delta[b,d,t] = softplus( sum_r Wd[d,r]*xdbl[b,r,t] + bias[d] )
// M=2048, N=1024, K=64
// =====================================================================
__global__ __launch_bounds__(256) void k_dtproj(const float* __restrict__ Wd,
                                                const float* __restrict__ bd,
                                                int dir) {
    __shared__ float As[8][128];
    __shared__ float Bs[8][128];
    const int tid = threadIdx.x;
    const int tx = tid & 15, ty = tid >> 4;
    const int bm = blockIdx.y * 128;
    const int bn = blockIdx.x * 128;
    const int b = blockIdx.z;
    const int ar = tid >> 1, ac = (tid & 1) * 4;
    const int kr = tid >> 5, nc = (tid & 31) * 4;
    const float* Bmat = g_xdbl[dir] + (size_t)b * 96 * L;   // rows 0..63 = dtr

    unsigned long long acc[8][4];
#pragma unroll
    for (int i = 0; i < 8; i++)
#pragma unroll
        for (int j = 0; j < 4; j++) acc[i][j] = 0ull;

    float4 av = *(const float4*)(Wd + (size_t)(bm + ar) * 64 + ac);
    float4 bv = *(const float4*)(Bmat + (size_t)kr * L + bn + nc);

    for (int k0 = 0; k0 < 64; k0 += 8) {
        As[ac + 0][ar] = av.x; As[ac + 1][ar] = av.y;
        As[ac + 2][ar] = av.z; As[ac + 3][ar] = av.w;
        *(float4*)&Bs[kr][nc] = bv;
        __syncthreads();
        if (k0 + 8 < 64) {
            av = *(const float4*)(Wd + (size_t)(bm + ar) * 64 + k0 + 8 + ac);
            bv = *(const float4*)(Bmat + (size_t)(k0 + 8 + kr) * L + bn + nc);
        }
        MICRO_KK(As, Bs, acc);
        __syncthreads();
    }

    float accf[8][8];
    UNPACK_ACC(acc, accf);

    float* dstb = g_delta[dir] + (size_t)b * DI * L;
#pragma unroll
    for (int i = 0; i < 8; i++) {
        int m = bm + ((i < 4) ? (ty * 4 + i) : (64 + ty * 4 + i - 4));
        float bias = bd[m];
        float4 v0 = make_float4(softplusf(accf[i][0] + bias), softplusf(accf[i][1] + bias),
                                softplusf(accf[i][2] + bias), softplusf(accf[i][3] + bias));
        float4 v1 = make_float4(softplusf(accf[i][4] + bias), softplusf(accf[i][5] + bias),
                                softplusf(accf[i][6] + bias), softplusf(accf[i][7] + bias));
        *(float4*)(dstb + (size_t)m * L + bn + tx * 4) = v0;
        *(float4*)(dstb + (size_t)m * L + bn + 64 + tx * 4) = v1;
    }
}

// =====================================================================
// Selective scan: half-warp per (b,d); lane n in [0,16) owns state n.
//  h_n = exp(delta*A_n)*h_n + delta*B_n*x ;  y = sum_n h_n*C_n + x*D
// =====================================================================
__global__ __launch_bounds__(256) void k_scan(const float* __restrict__ Alog,
                                              const float* __restrict__ Dp,
                                              int dir) {
    const int gt = blockIdx.x * 256 + threadIdx.x;
    const int n = gt & 15;
    const int p = gt >> 4;          // 0..4095  = b*DI + d
    const int b = p >> 11;
    const int d = p & 2047;

    const float An = -expf(Alog[d * DS + n]);
    const float Dd = Dp[d];
    const float* del = g_delta[dir] + ((size_t)(b * DI + d)) * L;
    const float* xx  = g_xconv[dir] + ((size_t)(b * DI + d)) * L;
    const float* Bm  = g_xdbl[dir]  + ((size_t)(b * 96 + 64 + n)) * L;
    const float* Cm  = g_xdbl[dir]  + ((size_t)(b * 96 + 80 + n)) * L;
    float* yo = g_y[dir] + ((size_t)(b * DI + d)) * L;

    float h = 0.f;
#pragma unroll 4
    for (int t = 0; t < L; t++) {
        float dl = del[t];
        float xv = xx[t];
        float dA = __expf(dl * An);
        h = fmaf(dA, h, dl * Bm[t] * xv);
        float s = h * Cm[t];
        s += __shfl_xor_sync(0xffffffffu, s, 1);
        s += __shfl_xor_sync(0xffffffffu, s, 2);
        s += __shfl_xor_sync(0xffffffffu, s, 4);
        s += __shfl_xor_sync(0xffffffffu, s, 8);
        if (n == 0) yo[t] = fmaf(xv, Dd, s);
    }
}

// =====================================================================
// Combine: comb[b,d,l] = 0.5*silu(z[b,d,l]) * (y_f[b,d,l] + y_b[b,d,L-1-l])
// =====================================================================
__global__ __launch_bounds__(256) void k_combine() {
    size_t idx = (size_t)blockIdx.x * 256 + threadIdx.x;  // over NB*DI*L
    int l = (int)(idx & 1023);
    size_t bd = idx >> 10;             // b*DI + d
    int b = (int)(bd >> 11);
    int d = (int)(bd & 2047);
    float z = g_xz[((size_t)(b * E2 + DI + d)) * L + l];
    float yf = g_y[0][idx];
    float yb = g_y[1][(bd << 10) + (size_t)(1023 - l)];
    g_comb[idx] = 0.5f * siluf(z) * (yf + yb);
}

// =====================================================================
// GEMM 4: Out[b,l,o] = sum_d comb[b,d,l] * Wo[o,d]
// M=2048 (b,l), N=1024 (o), K=2048. A is k-major (contiguous in m!).
// =====================================================================
__global__ __launch_bounds__(256) void k_outproj(const float* __restrict__ Wo,
                                                 float* __restrict__ Out) {
    __shared__ float As[8][128];
    __shared__ float Bs[8][128];
    const int tid = threadIdx.x;
    const int tx = tid & 15, ty = tid >> 4;
    const int bm = blockIdx.y * 128;
    const int bn = blockIdx.x * 128;
    const int ar = tid >> 1, ac = (tid & 1) * 4;
    const int kr = tid >> 5, mc = (tid & 31) * 4;
    const int bb = bm >> 10;
    const int l0 = bm & 1023;
    const float* Abase = g_comb + (size_t)bb * DI * L;

    unsigned long long acc[8][4];
#pragma unroll
    for (int i = 0; i < 8; i++)
#pragma unroll
        for (int j = 0; j < 4; j++) acc[i][j] = 0ull;

    float4 av = *(const float4*)(Abase + (size_t)kr * L + l0 + mc);
    float4 bv = *(const float4*)(Wo + (size_t)(bn + ar) * DI + ac);

    for (int k0 = 0; k0 < DI; k0 += 8) {
        *(float4*)&As[kr][mc] = av;
        Bs[ac + 0][ar] = bv.x; Bs[ac + 1][ar] = bv.y;
        Bs[ac + 2][ar] = bv.z; Bs[ac + 3][ar] = bv.w;
        __syncthreads();
        if (k0 + 8 < DI) {
            av = *(const float4*)(Abase + (size_t)(k0 + 8 + kr) * L + l0 + mc);
            bv = *(const float4*)(Wo + (size_t)(bn + ar) * DI + k0 + 8 + ac);
        }
        MICRO_KK(As, Bs, acc);
        __syncthreads();
    }

    float accf[8][8];
    UNPACK_ACC(acc, accf);

#pragma unroll
    for (int i = 0; i < 8; i++) {
        int m = bm + ((i < 4) ? (ty * 4 + i) : (64 + ty * 4 + i - 4));
        float4 v0 = make_float4(accf[i][0], accf[i][1], accf[i][2], accf[i][3]);
        float4 v1 = make_float4(accf[i][4], accf[i][5], accf[i][6], accf[i][7]);
        *(float4*)(Out + (size_t)m * DM + bn + tx * 4) = v0;
        *(float4*)(Out + (size_t)m * DM + bn + 64 + tx * 4) = v1;
    }
}

// =====================================================================
extern "C" void kernel_launch(void* const* d_in, const int* in_sizes, int n_in,
                              void* d_out, int out_size) {
    const float* hs   = (const float*)d_in[0];
    const float* Win  = (const float*)d_in[1];
    const float* cw[2]  = {(const float*)d_in[2],  (const float*)d_in[9]};
    const float* cb[2]  = {(const float*)d_in[3],  (const float*)d_in[10]};
    const float* xpw[2] = {(const float*)d_in[4],  (const float*)d_in[11]};
    const float* dtw[2] = {(const float*)d_in[5],  (const float*)d_in[12]};
    const float* dtb[2] = {(const float*)d_in[6],  (const float*)d_in[13]};
    const float* al[2]  = {(const float*)d_in[7],  (const float*)d_in[14]};
    const float* dp[2]  = {(const float*)d_in[8],  (const float*)d_in[15]};
    const float* Wout = (const float*)d_in[16];
    float* Out = (float*)d_out;

    k_inproj<<<dim3(32, 16), 256>>>(hs, Win);
    for (int dir = 0; dir < 2; dir++) {
        k_conv<<<dim3(4, DI, NB), 256>>>(cw[dir], cb[dir], dir);
        k_xproj<<<dim3(8, 1, NB), 256>>>(xpw[dir], dir);
        k_dtproj<<<dim3(8, 16, NB), 256>>>(dtw[dir], dtb[dir], dir);
        k_scan<<<256, 256>>>(al[dir], dp[dir], dir);
    }
    k_combine<<<16384, 256>>>();
    k_outproj<<<dim3(8, 16), 256>>>(Wout, Out);
}